// round 4
// baseline (speedup 1.0000x reference)
#include <cuda_runtime.h>
#include <cuda_bf16.h>

#define NN 4096
#define IN_DIM 6
#define HID 32
#define HEADS1 4
#define F1 128          // HEADS1*HID
#define OUT_DIM 64
#define MAXDEG 256      // mean deg ~41 (1% of 4096 + self), 256 is >30 sigma safe

// ---------------- device scratch (no allocations allowed) ----------------
__device__ float g_h1raw[NN * F1];
__device__ float g_e_src1[NN * HEADS1];
__device__ float g_e_dst1[NN * HEADS1];
__device__ float g_h1[NN * F1];
__device__ float g_h2raw[NN * OUT_DIM];
__device__ float g_e_src2[NN];
__device__ float g_e_dst2[NN];
__device__ int   g_deg[NN];
__device__ int   g_cols[NN * MAXDEG];

// ---------------- K1: h1raw = x @ W1 ; e_src1/e_dst1 ----------------
// grid NN, block 128. thread c owns output feature c (head=c/32, d=c%32).
__global__ void k1_proj1(const float* __restrict__ x,
                         const float* __restrict__ W1,
                         const float* __restrict__ a_src,
                         const float* __restrict__ a_dst) {
    int n = blockIdx.x;
    int c = threadIdx.x;
    __shared__ float xs[IN_DIM];
    if (c < IN_DIM) xs[c] = x[n * IN_DIM + c];
    __syncthreads();

    float hv = 0.f;
#pragma unroll
    for (int k = 0; k < IN_DIM; k++) hv += xs[k] * W1[k * F1 + c];
    g_h1raw[n * F1 + c] = hv;

    // per-head dot: warp w == head w (32 lanes == HID)
    float ps = hv * a_src[c];   // a_src flat [4*32] indexed by c
    float pd = hv * a_dst[c];
#pragma unroll
    for (int off = 16; off; off >>= 1) {
        ps += __shfl_down_sync(0xffffffffu, ps, off);
        pd += __shfl_down_sync(0xffffffffu, pd, off);
    }
    if ((c & 31) == 0) {
        int h = c >> 5;
        g_e_src1[n * HEADS1 + h] = ps;
        g_e_dst1[n * HEADS1 + h] = pd;
    }
}

// ---------------- K2: deterministic CSR build from dense adj ----------------
// grid NN, block 256. float4 loads: 4096 floats = 1024 float4 per row,
// thread t handles float4 chunks t, t+256, t+512, t+768 (4 iterations).
// Block prefix-sum of per-thread counts -> ordered, atomic-free compaction.
__global__ void k2_csr(const float* __restrict__ adj) {
    int i = blockIdx.x;
    int t = threadIdx.x;
    const float4* row4 = (const float4*)(adj + (size_t)i * NN);

    // pass 1: count
    int cnt = 0;
#pragma unroll
    for (int it = 0; it < 4; it++) {
        int q = t + it * 256;               // float4 index, 0..1023
        float4 v = row4[q];
        int j0 = q * 4;
        if (v.x > 0.f || j0 + 0 == i) cnt++;
        if (v.y > 0.f || j0 + 1 == i) cnt++;
        if (v.z > 0.f || j0 + 2 == i) cnt++;
        if (v.w > 0.f || j0 + 3 == i) cnt++;
    }

    __shared__ int s[256];
    s[t] = cnt;
    __syncthreads();
    // Hillis-Steele inclusive scan
    for (int off = 1; off < 256; off <<= 1) {
        int v = (t >= off) ? s[t - off] : 0;
        __syncthreads();
        s[t] += v;
        __syncthreads();
    }
    int total = s[255];
    int base = s[t] - cnt;   // exclusive prefix

    // pass 2: compaction in identical traversal order (L2-hot re-read)
    int w = 0;
#pragma unroll
    for (int it = 0; it < 4; it++) {
        int q = t + it * 256;
        float4 v = row4[q];
        int j0 = q * 4;
        float f[4] = {v.x, v.y, v.z, v.w};
#pragma unroll
        for (int u = 0; u < 4; u++) {
            if (f[u] > 0.f || j0 + u == i) {
                int slot = base + w;
                if (slot < MAXDEG) g_cols[i * MAXDEG + slot] = j0 + u;
                w++;
            }
        }
    }
    if (t == 0) g_deg[i] = (total < MAXDEG) ? total : MAXDEG;
}

// ---------------- K3: layer-1 sparse attention + aggregate + bias + ELU ----
// grid NN, block 128. thread c owns output feature c.
__global__ void k3_attn1(const float* __restrict__ b1) {
    int n = blockIdx.x;
    int t = threadIdx.x;
    int deg = g_deg[n];

    __shared__ int   cols_s[MAXDEG];
    __shared__ float w_s[MAXDEG * HEADS1];
    __shared__ float sinv[HEADS1];

    // pass A: logits per (neighbor, head), neighbors strided over 128 threads
    float es[HEADS1];
#pragma unroll
    for (int h = 0; h < HEADS1; h++) es[h] = g_e_src1[n * HEADS1 + h];

    for (int nbr = t; nbr < deg; nbr += 128) {
        int j = g_cols[n * MAXDEG + nbr];
        cols_s[nbr] = j;
#pragma unroll
        for (int h = 0; h < HEADS1; h++) {
            float l = es[h] + g_e_dst1[j * HEADS1 + h];
            l = (l > 0.f) ? l : 0.2f * l;           // leaky_relu(0.2)
            w_s[nbr * HEADS1 + h] = l;
        }
    }
    __syncthreads();

    // warp h reduces head h: max, then exp+sum in place
    int h = t >> 5, lane = t & 31;
    {
        float m = -1e30f;
        for (int nbr = lane; nbr < deg; nbr += 32)
            m = fmaxf(m, w_s[nbr * HEADS1 + h]);
#pragma unroll
        for (int off = 16; off; off >>= 1)
            m = fmaxf(m, __shfl_xor_sync(0xffffffffu, m, off));
        float ssum = 0.f;
        for (int nbr = lane; nbr < deg; nbr += 32) {
            float e = expf(w_s[nbr * HEADS1 + h] - m);
            w_s[nbr * HEADS1 + h] = e;
            ssum += e;
        }
#pragma unroll
        for (int off = 16; off; off >>= 1)
            ssum += __shfl_xor_sync(0xffffffffu, ssum, off);
        if (lane == 0) sinv[h] = 1.f / ssum;
    }
    __syncthreads();

    // pass B: weighted aggregation over neighbors (coalesced 512B per nbr)
    int head = t >> 5;
    float acc = 0.f;
    for (int nbr = 0; nbr < deg; nbr++) {
        acc += w_s[nbr * HEADS1 + head] * g_h1raw[cols_s[nbr] * F1 + t];
    }
    float o = acc * sinv[head] + b1[t];
    o = (o > 0.f) ? o : (expf(o) - 1.f);            // ELU alpha=1
    g_h1[n * F1 + t] = o;
}

// ---------------- K4: h2raw = h1 @ W2 ; e_src2/e_dst2 ----------------
// grid NN, block 64. thread c owns output feature c of 64.
__global__ void k4_proj2(const float* __restrict__ W2,
                         const float* __restrict__ a_src2,
                         const float* __restrict__ a_dst2) {
    int n = blockIdx.x;
    int c = threadIdx.x;
    __shared__ float hs[F1];
    hs[c] = g_h1[n * F1 + c];
    hs[c + 64] = g_h1[n * F1 + c + 64];
    __syncthreads();

    float hv = 0.f;
#pragma unroll 8
    for (int k = 0; k < F1; k++) hv += hs[k] * W2[k * OUT_DIM + c];
    g_h2raw[n * OUT_DIM + c] = hv;

    // single head over all 64 dims: reduce across 2 warps
    float ps = hv * a_src2[c];
    float pd = hv * a_dst2[c];
#pragma unroll
    for (int off = 16; off; off >>= 1) {
        ps += __shfl_down_sync(0xffffffffu, ps, off);
        pd += __shfl_down_sync(0xffffffffu, pd, off);
    }
    __shared__ float rs[2], rd[2];
    if ((c & 31) == 0) { rs[c >> 5] = ps; rd[c >> 5] = pd; }
    __syncthreads();
    if (c == 0) {
        g_e_src2[n] = rs[0] + rs[1];
        g_e_dst2[n] = rd[0] + rd[1];
    }
}

// ---------------- K5: layer-2 sparse attention + bias -> out ----------------
// grid NN, block 64.
__global__ void k5_attn2(const float* __restrict__ b2,
                         float* __restrict__ out) {
    int n = blockIdx.x;
    int t = threadIdx.x;
    int deg = g_deg[n];

    __shared__ int   cols_s[MAXDEG];
    __shared__ float w_s[MAXDEG];
    __shared__ float sinv_s;

    float es = g_e_src2[n];
    for (int nbr = t; nbr < deg; nbr += 64) {
        int j = g_cols[n * MAXDEG + nbr];
        cols_s[nbr] = j;
        float l = es + g_e_dst2[j];
        l = (l > 0.f) ? l : 0.2f * l;
        w_s[nbr] = l;
    }
    __syncthreads();

    // warp 0 reduces: max, exp, sum
    if (t < 32) {
        float m = -1e30f;
        for (int nbr = t; nbr < deg; nbr += 32) m = fmaxf(m, w_s[nbr]);
#pragma unroll
        for (int off = 16; off; off >>= 1)
            m = fmaxf(m, __shfl_xor_sync(0xffffffffu, m, off));
        float ssum = 0.f;
        for (int nbr = t; nbr < deg; nbr += 32) {
            float e = expf(w_s[nbr] - m);
            w_s[nbr] = e;
            ssum += e;
        }
#pragma unroll
        for (int off = 16; off; off >>= 1)
            ssum += __shfl_xor_sync(0xffffffffu, ssum, off);
        if (t == 0) sinv_s = 1.f / ssum;
    }
    __syncthreads();

    float inv = sinv_s;
    float acc = 0.f;
    for (int nbr = 0; nbr < deg; nbr++) {
        acc += w_s[nbr] * g_h2raw[cols_s[nbr] * OUT_DIM + t];
    }
    out[n * OUT_DIM + t] = acc * inv + b2[t];
}

// ---------------- launch ----------------
extern "C" void kernel_launch(void* const* d_in, const int* in_sizes, int n_in,
                              void* d_out, int out_size) {
    const float* x      = (const float*)d_in[0];
    const float* adj    = (const float*)d_in[1];
    const float* W1     = (const float*)d_in[2];
    const float* a_src1 = (const float*)d_in[3];
    const float* a_dst1 = (const float*)d_in[4];
    const float* b1     = (const float*)d_in[5];
    const float* W2     = (const float*)d_in[6];
    const float* a_src2 = (const float*)d_in[7];
    const float* a_dst2 = (const float*)d_in[8];
    const float* b2     = (const float*)d_in[9];
    float* out = (float*)d_out;

    k1_proj1<<<NN, 128>>>(x, W1, a_src1, a_dst1);
    k2_csr<<<NN, 256>>>(adj);
    k3_attn1<<<NN, 128>>>(b1);
    k4_proj2<<<NN, 64>>>(W2, a_src2, a_dst2);
    k5_attn2<<<NN, 64>>>(b2, out);
}